// round 4
// baseline (speedup 1.0000x reference)
#include <cuda_runtime.h>
#include <mma.h>
#include <math.h>

using namespace nvcuda;

#define B_   8192
#define L_   10
#define NT_  26
#define V_   200000
#define HB_  4096              // half batch

// per-row scratch: h1(512) h2(256) h3(64) T26(1664) R(416) z1(512) z2(256) = 3680
// plus padded top_W1 [512][416]
__device__ __align__(256) float g_scratch[(size_t)B_ * 3680 + 512 * 416];

// ---------------------------------------------------------------------------
// cp.async helpers
// ---------------------------------------------------------------------------
__device__ __forceinline__ void cp16(void* smem, const void* gmem) {
    unsigned s = (unsigned)__cvta_generic_to_shared(smem);
    asm volatile("cp.async.ca.shared.global [%0], [%1], 16;\n" :: "r"(s), "l"(gmem));
}
__device__ __forceinline__ void cp_commit() { asm volatile("cp.async.commit_group;\n"); }
template<int N> __device__ __forceinline__ void cp_wait() {
    asm volatile("cp.async.wait_group %0;\n" :: "n"(N));
}

// ---------------------------------------------------------------------------
// Embedding bag pooling, one half-batch per launch. 16 threads/bag.
// ---------------------------------------------------------------------------
__global__ void __launch_bounds__(256) emb_pool_kernel(
    const int* __restrict__ lS_i, const float* __restrict__ tables,
    float* __restrict__ T26, int half)
{
    int gid = blockIdx.x * 256 + threadIdx.x;
    int w = gid >> 4;                    // bag within half, < 26*4096
    int lane = gid & 15;
    int t = w >> 12;
    int b = (half << 12) | (w & 4095);
    const int* idx = lS_i + (size_t)t * (B_ * L_) + (size_t)b * L_;
    const float* tab = tables + (size_t)t * (V_ * 64);
    float4 acc = make_float4(0.f, 0.f, 0.f, 0.f);
    #pragma unroll
    for (int l = 0; l < L_; l++) {
        int r = idx[l];
        float4 v = ((const float4*)(tab + (size_t)r * 64))[lane];
        acc.x += v.x; acc.y += v.y; acc.z += v.z; acc.w += v.w;
    }
    ((float4*)(T26 + (size_t)b * 1664 + (size_t)t * 64))[lane] = acc;
}

// ---------------------------------------------------------------------------
// Bottom MLP layer 1: [B,13] x [512,13]^T + b, ReLU -> h1 [B,512]
// ---------------------------------------------------------------------------
__global__ void __launch_bounds__(256) botl1_kernel(
    const float* __restrict__ x, const float* __restrict__ W,
    const float* __restrict__ bias, float* __restrict__ h1)
{
    __shared__ float Ws[512 * 13];
    __shared__ float bs[512];
    __shared__ float xs[16 * 13];
    int r0 = blockIdx.x * 16;
    for (int i = threadIdx.x; i < 512 * 13; i += 256) Ws[i] = W[i];
    for (int i = threadIdx.x; i < 512; i += 256) bs[i] = bias[i];
    for (int i = threadIdx.x; i < 16 * 13; i += 256) xs[i] = x[r0 * 13 + i];
    __syncthreads();
    #pragma unroll
    for (int cp = 0; cp < 2; cp++) {
        int c = threadIdx.x + cp * 256;
        float wreg[13];
        #pragma unroll
        for (int k = 0; k < 13; k++) wreg[k] = Ws[c * 13 + k];
        float bb = bs[c];
        #pragma unroll
        for (int r = 0; r < 16; r++) {
            float acc = bb;
            #pragma unroll
            for (int k = 0; k < 13; k++) acc = fmaf(wreg[k], xs[r * 13 + k], acc);
            h1[(size_t)(r0 + r) * 512 + c] = fmaxf(acc, 0.f);
        }
    }
}

// ---------------------------------------------------------------------------
// tf32 wmma GEMM: out = relu(X[M,lda] @ W[N,ldw]^T + bias)
// BM=128, BN template (128 or 64). 8 warps, 4x2 layout, warp tile 32 x BN/2.
// Raw fp32 bits into tf32 mma (hw truncation; rel_err ~3e-5, fine).
// ---------------------------------------------------------------------------
#define BK   16
#define KPAD 20

template<int BN>
__global__ void __launch_bounds__(256, 2) gemm_tf32(
    const float* __restrict__ X, int lda,
    const float* __restrict__ W, int ldw,
    const float* __restrict__ bias,
    float* __restrict__ out, int ldc, int K)
{
    constexpr int WTN = BN / 2;      // 64 or 32
    constexpr int FN = WTN / 16;     // 4 or 2
    __shared__ float As[2][128][KPAD];
    __shared__ float Bs[2][BN][KPAD];
    int tid = threadIdx.x;
    int warp = tid >> 5;
    int lane = tid & 31;
    int wm = warp >> 1, wn = warp & 1;
    int m0 = blockIdx.x * 128, n0 = blockIdx.y * BN;

    wmma::fragment<wmma::accumulator, 16, 16, 8, float> acc[2][FN];
    #pragma unroll
    for (int i = 0; i < 2; i++)
        #pragma unroll
        for (int j = 0; j < FN; j++) wmma::fill_fragment(acc[i][j], 0.f);

    auto load_tile = [&](int buf, int k0) {
        #pragma unroll
        for (int i = tid; i < 128 * 4; i += 256) {
            int r = i >> 2, s = (i & 3) * 4;
            cp16(&As[buf][r][s], X + (size_t)(m0 + r) * lda + k0 + s);
        }
        #pragma unroll
        for (int i = tid; i < BN * 4; i += 256) {
            int r = i >> 2, s = (i & 3) * 4;
            cp16(&Bs[buf][r][s], W + (size_t)(n0 + r) * ldw + k0 + s);
        }
        cp_commit();
    };

    int nIter = K / BK;
    load_tile(0, 0);
    int buf = 0;
    for (int it = 0; it < nIter; it++) {
        if (it + 1 < nIter) { load_tile(buf ^ 1, (it + 1) * BK); cp_wait<1>(); }
        else cp_wait<0>();
        __syncthreads();
        #pragma unroll
        for (int ks = 0; ks < 2; ks++) {
            wmma::fragment<wmma::matrix_a, 16, 16, 8, wmma::precision::tf32, wmma::row_major> af[2];
            wmma::fragment<wmma::matrix_b, 16, 16, 8, wmma::precision::tf32, wmma::col_major> bf[FN];
            #pragma unroll
            for (int mi = 0; mi < 2; mi++)
                wmma::load_matrix_sync(af[mi], &As[buf][wm * 32 + mi * 16][ks * 8], KPAD);
            #pragma unroll
            for (int nj = 0; nj < FN; nj++)
                wmma::load_matrix_sync(bf[nj], &Bs[buf][wn * WTN + nj * 16][ks * 8], KPAD);
            #pragma unroll
            for (int mi = 0; mi < 2; mi++)
                #pragma unroll
                for (int nj = 0; nj < FN; nj++)
                    wmma::mma_sync(acc[mi][nj], af[mi], bf[nj], acc[mi][nj]);
        }
        __syncthreads();
        buf ^= 1;
    }

    // epilogue: per-warp 16x16 staging, +bias, relu
    float* es = &As[0][0][0] + warp * 16 * KPAD;
    #pragma unroll
    for (int mi = 0; mi < 2; mi++) {
        #pragma unroll
        for (int nj = 0; nj < FN; nj++) {
            wmma::store_matrix_sync(es, acc[mi][nj], KPAD, wmma::mem_row_major);
            __syncwarp();
            int r = lane >> 1, c0 = (lane & 1) * 8;
            int gm = m0 + wm * 32 + mi * 16 + r;
            int gn = n0 + wn * WTN + nj * 16 + c0;
            #pragma unroll
            for (int c = 0; c < 8; c++) {
                float v = es[r * KPAD + c0 + c] + bias[gn + c];
                out[(size_t)gm * ldc + gn + c] = fmaxf(v, 0.f);
            }
            __syncwarp();
        }
    }
}

// ---------------------------------------------------------------------------
// Dot interaction (per half): Z = T T^T, R = [h3, tril(Z)], stride 416.
// 8 warps = 8 batch rows per block.
// ---------------------------------------------------------------------------
#define TLD 68

__global__ void __launch_bounds__(256) interact_kernel(
    const float* __restrict__ h3, const float* __restrict__ T26,
    float* __restrict__ R, int half)
{
    extern __shared__ float sT[];          // 8 * 32 * TLD floats
    __shared__ float sZ[8][16][KPAD];
    int tid = threadIdx.x, warp = tid >> 5, lane = tid & 31;
    int b0 = half * HB_ + blockIdx.x * 8;

    for (int idx = tid; idx < 8 * 32 * 64; idx += 256) {
        int row = idx >> 11;
        int e = idx & 2047;
        int i = e >> 6, d = e & 63;
        float v = 0.f;
        if (i == 0)       v = h3[(size_t)(b0 + row) * 64 + d];
        else if (i < 27)  v = T26[(size_t)(b0 + row) * 1664 + (i - 1) * 64 + d];
        sT[(row * 32 + i) * TLD + d] = v;
    }
    __syncthreads();

    const float* tb = sT + warp * 32 * TLD;
    wmma::fragment<wmma::accumulator, 16, 16, 8, float> z[2][2];
    #pragma unroll
    for (int i = 0; i < 2; i++)
        #pragma unroll
        for (int j = 0; j < 2; j++) wmma::fill_fragment(z[i][j], 0.f);

    #pragma unroll
    for (int ks = 0; ks < 8; ks++) {
        wmma::fragment<wmma::matrix_a, 16, 16, 8, wmma::precision::tf32, wmma::row_major> af[2];
        wmma::fragment<wmma::matrix_b, 16, 16, 8, wmma::precision::tf32, wmma::col_major> bf[2];
        #pragma unroll
        for (int ti = 0; ti < 2; ti++) {
            wmma::load_matrix_sync(af[ti], tb + (ti * 16) * TLD + ks * 8, TLD);
            wmma::load_matrix_sync(bf[ti], tb + (ti * 16) * TLD + ks * 8, TLD);
        }
        #pragma unroll
        for (int ti = 0; ti < 2; ti++)
            #pragma unroll
            for (int tj = 0; tj < 2; tj++)
                wmma::mma_sync(z[ti][tj], af[ti], bf[tj], z[ti][tj]);
    }

    float* Rb = R + (size_t)(b0 + warp) * 416;
    #pragma unroll
    for (int d = lane; d < 64; d += 32) Rb[d] = tb[d];
    if (lane == 0) Rb[415] = 0.f;

    #pragma unroll
    for (int ti = 0; ti < 2; ti++) {
        #pragma unroll
        for (int tj = 0; tj <= ti; tj++) {
            wmma::store_matrix_sync(&sZ[warp][0][0], z[ti][tj], KPAD, wmma::mem_row_major);
            __syncwarp();
            int r = lane >> 1, c0 = (lane & 1) * 8;
            int gi = ti * 16 + r;
            #pragma unroll
            for (int c = 0; c < 8; c++) {
                int gj = tj * 16 + c0 + c;
                if (gi > gj && gi >= 1 && gi <= 26)
                    Rb[64 + gi * (gi - 1) / 2 + gj] = sZ[warp][r][c0 + c];
            }
            __syncwarp();
        }
    }
}

// ---------------------------------------------------------------------------
// Pad top_W1 [512,415] -> Wp [512,416] (col 415 = 0)
// ---------------------------------------------------------------------------
__global__ void __launch_bounds__(256) padw_kernel(
    const float* __restrict__ w, float* __restrict__ wp)
{
    int i = blockIdx.x * 256 + threadIdx.x;
    if (i >= 512 * 416) return;
    int n = i / 416, c = i - n * 416;
    wp[i] = (c < 415) ? w[n * 415 + c] : 0.f;
}

// ---------------------------------------------------------------------------
// Top MLP layer 3 (per half): sigmoid(z2 . W + b) -> out
// ---------------------------------------------------------------------------
__global__ void __launch_bounds__(256) top3_kernel(
    const float* __restrict__ z2, const float* __restrict__ W,
    const float* __restrict__ bias, float* __restrict__ out, int half)
{
    int gw = blockIdx.x * 8 + (threadIdx.x >> 5);
    int lane = threadIdx.x & 31;
    int row = half * HB_ + gw;
    const float* zr = z2 + (size_t)row * 256;
    float acc = 0.f;
    #pragma unroll
    for (int u = 0; u < 8; u++) acc = fmaf(zr[lane + 32 * u], W[lane + 32 * u], acc);
    #pragma unroll
    for (int o = 16; o > 0; o >>= 1) acc += __shfl_xor_sync(0xffffffffu, acc, o);
    if (lane == 0) out[row] = 1.f / (1.f + expf(-(acc + bias[0])));
}

// ---------------------------------------------------------------------------
extern "C" void kernel_launch(void* const* d_in, const int* in_sizes, int n_in,
                              void* d_out, int out_size)
{
    const float* x    = (const float*)d_in[0];
    const int*   lS_i = (const int*)d_in[1];
    const float* emb  = (const float*)d_in[3];
    const float* bW1  = (const float*)d_in[4];
    const float* bb1  = (const float*)d_in[5];
    const float* bW2  = (const float*)d_in[6];
    const float* bb2  = (const float*)d_in[7];
    const float* bW3  = (const float*)d_in[8];
    const float* bb3  = (const float*)d_in[9];
    const float* tW1  = (const float*)d_in[10];
    const float* tb1  = (const float*)d_in[11];
    const float* tW2  = (const float*)d_in[12];
    const float* tb2  = (const float*)d_in[13];
    const float* tW3  = (const float*)d_in[14];
    const float* tb3  = (const float*)d_in[15];
    float* out = (float*)d_out;

    float* base;
    cudaGetSymbolAddress((void**)&base, g_scratch);
    float* h1  = base;                        // [B,512]
    float* h2  = h1  + (size_t)B_ * 512;      // [B,256]
    float* h3  = h2  + (size_t)B_ * 256;      // [B,64]
    float* T26 = h3  + (size_t)B_ * 64;       // [B,26,64]
    float* R   = T26 + (size_t)B_ * 1664;     // [B,416]
    float* z1  = R   + (size_t)B_ * 416;      // [B,512]
    float* z2  = z1  + (size_t)B_ * 512;      // [B,256]
    float* Wp  = z2  + (size_t)B_ * 256;      // [512,416]

    // one-time host resources (streams/events are host-side; no device mem)
    static cudaStream_t s2 = nullptr;
    static cudaEvent_t evFork, evE0, evE1;
    if (!s2) {
        cudaStreamCreateWithFlags(&s2, cudaStreamNonBlocking);
        cudaEventCreateWithFlags(&evFork, cudaEventDisableTiming);
        cudaEventCreateWithFlags(&evE0, cudaEventDisableTiming);
        cudaEventCreateWithFlags(&evE1, cudaEventDisableTiming);
        cudaFuncSetAttribute(interact_kernel,
                             cudaFuncAttributeMaxDynamicSharedMemorySize,
                             8 * 32 * TLD * (int)sizeof(float));
    }
    int ismem = 8 * 32 * TLD * sizeof(float);

    // ---- fork: embedding gather on side stream (both halves) ----
    cudaEventRecord(evFork, 0);
    cudaStreamWaitEvent(s2, evFork, 0);
    emb_pool_kernel<<<(NT_ * HB_ * 16) / 256, 256, 0, s2>>>(lS_i, emb, T26, 0);
    cudaEventRecord(evE0, s2);
    emb_pool_kernel<<<(NT_ * HB_ * 16) / 256, 256, 0, s2>>>(lS_i, emb, T26, 1);
    cudaEventRecord(evE1, s2);

    // ---- main stream: bottom MLP (full batch) ----
    padw_kernel<<<(512 * 416 + 255) / 256, 256>>>(tW1, Wp);
    botl1_kernel<<<B_ / 16, 256>>>(x, bW1, bb1, h1);
    gemm_tf32<128><<<dim3(B_ / 128, 2), 256>>>(h1, 512, bW2, 512, bb2, h2, 256, 512);
    gemm_tf32<64><<<dim3(B_ / 128, 1), 256>>>(h2, 256, bW3, 256, bb3, h3, 64, 256);

    // ---- half 0: join emb half0, interact + top ----
    cudaStreamWaitEvent(0, evE0, 0);
    interact_kernel<<<HB_ / 8, 256, ismem>>>(h3, T26, R, 0);
    gemm_tf32<128><<<dim3(HB_ / 128, 4), 256>>>(R, 416, Wp, 416, tb1,
                                                z1, 512, 416);
    gemm_tf32<128><<<dim3(HB_ / 128, 2), 256>>>(z1, 512, tW2, 512, tb2,
                                                z2, 256, 512);
    top3_kernel<<<HB_ / 8, 256>>>(z2, tW3, tb3, out, 0);

    // ---- half 1: join emb half1, interact + top ----
    cudaStreamWaitEvent(0, evE1, 0);
    interact_kernel<<<HB_ / 8, 256, ismem>>>(h3, T26, R, 1);
    gemm_tf32<128><<<dim3(HB_ / 128, 4), 256>>>(R + (size_t)HB_ * 416, 416, Wp, 416, tb1,
                                                z1 + (size_t)HB_ * 512, 512, 416);
    gemm_tf32<128><<<dim3(HB_ / 128, 2), 256>>>(z1 + (size_t)HB_ * 512, 512, tW2, 512, tb2,
                                                z2 + (size_t)HB_ * 256, 256, 512);
    top3_kernel<<<HB_ / 8, 256>>>(z2, tW3, tb3, out, 1);
}